// round 6
// baseline (speedup 1.0000x reference)
#include <cuda_runtime.h>
#include <cuda_bf16.h>
#include <cstdint>

#define NN   200000
#define NE   400000
#define DIM  128
#define NL   5
#define NG   1000
#define BONDV 5
#define NBLK 782           // ceil(NN/256)
#define NTILE 1563         // ceil(NN/128)
#define ROW_BYTES 256      // 128 bf16 per row

// ---------------- device scratch ----------------
__device__ float g_y[2 * NN * DIM];   // ping-pong node features (pre-BN y)
__device__ float g_deg[NN];
__device__ float g_stats[2 * DIM];    // column sum / sumsq (self-rezeroing)
__device__ float g_bnp[2 * DIM];      // BN scale / shift
__device__ int   g_cnti[NN];
__device__ int   g_off[NN + 1];
__device__ int   g_cur[NN];
__device__ int   g_blk[NBLK];
__device__ int   g_edge[NE];          // packed (src<<3)|efeat
__device__ unsigned char g_wh[NL * DIM * ROW_BYTES];  // W^T hi: [n][k] bf16
__device__ unsigned char g_wl[NL * DIM * ROW_BYTES];  // W^T lo

// bf16 hi/lo split of a float pair, packed (low half = first element)
__device__ __forceinline__ void bsplit(float a, float b, uint32_t& hi, uint32_t& lo) {
    __nv_bfloat162 h = __float22bfloat162_rn(make_float2(a, b));
    float2 hf = __bfloat1622float2(h);
    __nv_bfloat162 l = __float22bfloat162_rn(make_float2(a - hf.x, b - hf.y));
    hi = *(uint32_t*)&h;
    lo = *(uint32_t*)&l;
}

__device__ __forceinline__ uint32_t smem_u32(const void* p) {
    uint32_t a;
    asm("{ .reg .u64 t; cvta.to.shared.u64 t, %1; cvt.u32.u64 %0, t; }"
        : "=r"(a) : "l"(p));
    return a;
}
__device__ __forceinline__ void ldsm4(uint32_t& r0, uint32_t& r1, uint32_t& r2,
                                      uint32_t& r3, uint32_t addr) {
    asm volatile("ldmatrix.sync.aligned.m8n8.x4.shared.b16 {%0,%1,%2,%3}, [%4];"
                 : "=r"(r0), "=r"(r1), "=r"(r2), "=r"(r3) : "r"(addr));
}
__device__ __forceinline__ void mma16816(float* d, uint32_t a0, uint32_t a1,
                                         uint32_t a2, uint32_t a3,
                                         uint32_t b0, uint32_t b1) {
    asm volatile(
        "mma.sync.aligned.m16n8k16.row.col.f32.bf16.bf16.f32 "
        "{%0,%1,%2,%3}, {%4,%5,%6,%7}, {%8,%9}, {%0,%1,%2,%3};"
        : "+f"(d[0]), "+f"(d[1]), "+f"(d[2]), "+f"(d[3])
        : "r"(a0), "r"(a1), "r"(a2), "r"(a3), "r"(b0), "r"(b1));
}

// ---------------- setup kernels ----------------
__global__ void k_init(const int* __restrict__ nfeat,
                       const float* __restrict__ atom_emb) {
    int idx = blockIdx.x * blockDim.x + threadIdx.x;
    if (idx >= NN * 32) return;
    int node = idx >> 5, c = idx & 31;
    int a = nfeat[node];
    ((float4*)g_y)[node * 32 + c] = ((const float4*)atom_emb)[a * 32 + c];
    if (c == 0) g_cnti[node] = 0;
}

__global__ void k_hist(const int* __restrict__ dst) {
    int e = blockIdx.x * blockDim.x + threadIdx.x;
    if (e < NE) atomicAdd(&g_cnti[dst[e]], 1);
}

__global__ void k_scan1() {
    __shared__ int s[256];
    int i = blockIdx.x * 256 + threadIdx.x;
    int c = (i < NN) ? g_cnti[i] : 0;
    s[threadIdx.x] = c;
    __syncthreads();
    int v = c;
#pragma unroll
    for (int d = 1; d < 256; d <<= 1) {
        int t = (threadIdx.x >= d) ? s[threadIdx.x - d] : 0;
        __syncthreads();
        v += t;
        s[threadIdx.x] = v;
        __syncthreads();
    }
    if (i < NN) g_off[i] = v - c;
    if (threadIdx.x == 255) g_blk[blockIdx.x] = v;
}

__global__ void k_scan2() {
    __shared__ int s[1024];
    int t = threadIdx.x;
    int c = (t < NBLK) ? g_blk[t] : 0;
    s[t] = c;
    __syncthreads();
    int v = c;
#pragma unroll
    for (int d = 1; d < 1024; d <<= 1) {
        int x = (t >= d) ? s[t - d] : 0;
        __syncthreads();
        v += x;
        s[t] = v;
        __syncthreads();
    }
    if (t < NBLK) g_blk[t] = v - c;
}

__global__ void k_scan3() {
    int i = blockIdx.x * blockDim.x + threadIdx.x;
    if (i >= NN) return;
    int off = g_off[i] + g_blk[i >> 8];
    g_off[i] = off;
    g_cur[i] = off;
    g_deg[i] = 1.0f / (float)(g_cnti[i] + 1);
    if (i == 0) g_off[NN] = NE;
}

__global__ void k_fill(const int* __restrict__ src, const int* __restrict__ dst,
                       const int* __restrict__ efeat) {
    int e = blockIdx.x * blockDim.x + threadIdx.x;
    if (e >= NE) return;
    int d = dst[e];
    int pos = atomicAdd(&g_cur[d], 1);
    g_edge[pos] = (src[e] << 3) | efeat[e];
}

// W^T images: BT[n][k] = W[k][n], bf16 hi/lo row-major
__global__ void k_wconv(const float* __restrict__ W) {
    int l = blockIdx.x, t = threadIdx.x;  // t = n
    const float* Wl = W + (size_t)l * DIM * DIM;
    unsigned char* wh = g_wh + (size_t)l * DIM * ROW_BYTES;
    unsigned char* wl = g_wl + (size_t)l * DIM * ROW_BYTES;
    for (int k = 0; k < DIM; k += 2) {
        uint32_t hi, lo;
        bsplit(Wl[k * DIM + t], Wl[(k + 1) * DIM + t], hi, lo);
        uint32_t byte = (uint32_t)(t * ROW_BYTES + k * 2);
        *(uint32_t*)(wh + byte) = hi;
        *(uint32_t*)(wl + byte) = lo;
    }
}

// ---------------- fused layer kernel ----------------
// Phase 1 (aggregate): each warp builds 16 rows of the bf16 hi/lo A image in
//   smem: A[n] = (h[n] + sum_in (h[src]+eemb[f])) * deg_inv, h = BN?relu(y*sc+sh):y
// Phase 2 (MMA): 3-term bf16-split 128x128x128 GEMM + bias + column stats.
#define PITCH 272                 // smem row pitch (17 x 16B, conflict-free ldmatrix)
#define IMG_SM (128 * PITCH)      // 34816
#define SM_BIAS 0
#define SM_SUM  512
#define SM_SQ   1024
#define SM_SE   1536                       // BONDV*DIM*4 = 2560
#define SM_AH   (SM_SE + 2560)             // 4096
#define SM_AL   (SM_AH + IMG_SM)
#define SM_WH   (SM_AL + IMG_SM)
#define SM_WL   (SM_WH + IMG_SM)
#define SM_TOTAL (SM_WL + IMG_SM)          // 143360

template <bool BN>
__global__ void __launch_bounds__(256, 1) k_layer(int layer,
                                                  const float* __restrict__ eembL,
                                                  const float* __restrict__ bl,
                                                  const float* __restrict__ yin,
                                                  float* __restrict__ yout) {
    extern __shared__ char smem[];
    uint32_t sb = smem_u32(smem);
    int tid = threadIdx.x, wid = tid >> 5, lane = tid & 31;

    float* sbias = (float*)(smem + SM_BIAS);
    float* ssum  = (float*)(smem + SM_SUM);
    float* ssq   = (float*)(smem + SM_SQ);
    if (tid < 128) {
        sbias[tid] = bl[tid];
        ssum[tid] = 0.f;
        ssq[tid] = 0.f;
    }
    if (tid < BONDV * 32)
        ((float4*)(smem + SM_SE))[tid] = ((const float4*)eembL)[tid];

    // stage W images: global row-major (256B rows) -> smem pitched (272B)
    {
        const float4* swh = (const float4*)(g_wh + (size_t)layer * DIM * ROW_BYTES);
        const float4* swl = (const float4*)(g_wl + (size_t)layer * DIM * ROW_BYTES);
#pragma unroll
        for (int i = 0; i < 8; i++) {
            int idx = tid + i * 256;        // 2048 float4 per image
            int row = idx >> 4, q = idx & 15;
            int soff = row * (PITCH / 16) + q;
            ((float4*)(smem + SM_WH))[soff] = swh[idx];
            ((float4*)(smem + SM_WL))[soff] = swl[idx];
        }
    }
    __syncthreads();  // se visible before aggregate reads it

    // ---- phase 1: aggregate 16 rows per warp into smem A images ----
    {
        const float4* y4 = (const float4*)yin;
        const float4* se4 = (const float4*)(smem + SM_SE);
        float4 sc, sh;
        if (BN) {
            sc = ((const float4*)g_bnp)[lane];
            sh = ((const float4*)(g_bnp + DIM))[lane];
        }
#pragma unroll 1
        for (int i = 0; i < 16; i++) {
            int r = wid * 16 + i;
            int n = blockIdx.x * 128 + r;
            if (n >= NN) break;   // tail rows: image garbage is masked in epilogue

            float4 acc;
            {
                float4 v = y4[(size_t)n * 32 + lane];
                if (BN) {
                    acc.x = fmaxf(fmaf(v.x, sc.x, sh.x), 0.f);
                    acc.y = fmaxf(fmaf(v.y, sc.y, sh.y), 0.f);
                    acc.z = fmaxf(fmaf(v.z, sc.z, sh.z), 0.f);
                    acc.w = fmaxf(fmaf(v.w, sc.w, sh.w), 0.f);
                } else acc = v;
            }
            int p0 = g_off[n], p1 = g_off[n + 1];
            for (int p = p0; p < p1; p++) {
                int pk = g_edge[p];
                int s = pk >> 3, f = pk & 7;
                float4 v = y4[(size_t)s * 32 + lane];
                float4 ev = se4[f * 32 + lane];
                if (BN) {
                    acc.x += fmaxf(fmaf(v.x, sc.x, sh.x), 0.f) + ev.x;
                    acc.y += fmaxf(fmaf(v.y, sc.y, sh.y), 0.f) + ev.y;
                    acc.z += fmaxf(fmaf(v.z, sc.z, sh.z), 0.f) + ev.z;
                    acc.w += fmaxf(fmaf(v.w, sc.w, sh.w), 0.f) + ev.w;
                } else {
                    acc.x += v.x + ev.x;
                    acc.y += v.y + ev.y;
                    acc.z += v.z + ev.z;
                    acc.w += v.w + ev.w;
                }
            }
            float dinv = g_deg[n];
            acc.x *= dinv; acc.y *= dinv; acc.z *= dinv; acc.w *= dinv;

            uint2 hi2, lo2;
            bsplit(acc.x, acc.y, hi2.x, lo2.x);
            bsplit(acc.z, acc.w, hi2.y, lo2.y);
            *(uint2*)(smem + SM_AH + r * PITCH + lane * 8) = hi2;
            *(uint2*)(smem + SM_AL + r * PITCH + lane * 8) = lo2;
        }
    }
    __syncthreads();

    // ---- phase 2: MMA ----
    int g = lane >> 2, tg = lane & 3;
    uint32_t a_row = 16 * wid + (lane & 15);
    uint32_t a_kof = (lane >> 4) * 16;
    uint32_t ah_base = sb + SM_AH + a_row * PITCH + a_kof;
    uint32_t al_base = sb + SM_AL + a_row * PITCH + a_kof;
    uint32_t b_row = ((lane >> 4) << 3) + (lane & 7);
    uint32_t b_kof = ((lane >> 3) & 1) * 16;
    uint32_t wh_base = sb + SM_WH + b_row * PITCH + b_kof;
    uint32_t wl_base = sb + SM_WL + b_row * PITCH + b_kof;

    float d[16][4];
#pragma unroll
    for (int i = 0; i < 16; i++)
#pragma unroll
        for (int j = 0; j < 4; j++) d[i][j] = 0.f;

#pragma unroll
    for (int ks = 0; ks < 8; ks++) {
        uint32_t ah0, ah1, ah2, ah3, al0, al1, al2, al3;
        ldsm4(ah0, ah1, ah2, ah3, ah_base + ks * 32);
        ldsm4(al0, al1, al2, al3, al_base + ks * 32);
#pragma unroll
        for (int nt2 = 0; nt2 < 8; nt2++) {
            uint32_t bh0, bh1, bh2, bh3, bl0_, bl1_, bl2_, bl3_;
            uint32_t off = nt2 * 16 * PITCH + ks * 32;
            ldsm4(bh0, bh1, bh2, bh3, wh_base + off);
            ldsm4(bl0_, bl1_, bl2_, bl3_, wl_base + off);
            mma16816(d[2 * nt2], ah0, ah1, ah2, ah3, bh0, bh1);
            mma16816(d[2 * nt2], al0, al1, al2, al3, bh0, bh1);
            mma16816(d[2 * nt2], ah0, ah1, ah2, ah3, bl0_, bl1_);
            mma16816(d[2 * nt2 + 1], ah0, ah1, ah2, ah3, bh2, bh3);
            mma16816(d[2 * nt2 + 1], al0, al1, al2, al3, bh2, bh3);
            mma16816(d[2 * nt2 + 1], ah0, ah1, ah2, ah3, bl2_, bl3_);
        }
    }

    // epilogue: bias, masked store, column stats
    int row0 = blockIdx.x * 128 + 16 * wid + g;
    int row1 = row0 + 8;
    bool v0 = row0 < NN, v1 = row1 < NN;

#pragma unroll
    for (int nt = 0; nt < 16; nt++) {
        int c0 = nt * 8 + 2 * tg;
        float b0 = sbias[c0], b1 = sbias[c0 + 1];
        float y0 = d[nt][0] + b0, y1 = d[nt][1] + b1;
        float y2 = d[nt][2] + b0, y3 = d[nt][3] + b1;
        if (!v0) { y0 = 0.f; y1 = 0.f; }
        if (!v1) { y2 = 0.f; y3 = 0.f; }
        if (v0) *(float2*)&yout[(size_t)row0 * DIM + c0] = make_float2(y0, y1);
        if (v1) *(float2*)&yout[(size_t)row1 * DIM + c0] = make_float2(y2, y3);

        float s0 = y0 + y2, s1 = y1 + y3;
        float q0 = y0 * y0 + y2 * y2, q1 = y1 * y1 + y3 * y3;
#pragma unroll
        for (int m = 4; m <= 16; m <<= 1) {
            s0 += __shfl_xor_sync(0xffffffffu, s0, m);
            s1 += __shfl_xor_sync(0xffffffffu, s1, m);
            q0 += __shfl_xor_sync(0xffffffffu, q0, m);
            q1 += __shfl_xor_sync(0xffffffffu, q1, m);
        }
        if (lane < 4) {
            atomicAdd(&ssum[c0], s0);
            atomicAdd(&ssum[c0 + 1], s1);
            atomicAdd(&ssq[c0], q0);
            atomicAdd(&ssq[c0 + 1], q1);
        }
    }
    __syncthreads();
    if (tid < 128) {
        atomicAdd(&g_stats[tid], ssum[tid]);
        atomicAdd(&g_stats[DIM + tid], ssq[tid]);
    }
}

// finalize BN params; re-zero stats (replay-safe)
__global__ void k_bnstat(const float* __restrict__ gammaL,
                         const float* __restrict__ betaL) {
    int t = threadIdx.x;  // 128
    float mu  = g_stats[t] * (1.0f / NN);
    float var = g_stats[DIM + t] * (1.0f / NN) - mu * mu;
    float rstd = rsqrtf(var + 1e-5f);
    float sc = rstd * gammaL[t];
    g_bnp[t] = sc;
    g_bnp[DIM + t] = betaL[t] - mu * sc;
    g_stats[t] = 0.f;
    g_stats[DIM + t] = 0.f;
}

// ---------------- fused pool + MLP (n2g sorted); applies final BN+relu ------
__device__ __forceinline__ int lbound(const int* __restrict__ a, int n, int key) {
    int lo = 0, hi = n;
    while (lo < hi) {
        int mid = (lo + hi) >> 1;
        if (a[mid] < key) lo = mid + 1; else hi = mid;
    }
    return lo;
}

__global__ void __launch_bounds__(128) k_poolmlp(const int* __restrict__ n2g,
                                                 const float* __restrict__ yin,
                                                 const float* __restrict__ W1,
                                                 const float* __restrict__ b1,
                                                 const float* __restrict__ W2,
                                                 const float* __restrict__ b2,
                                                 float* __restrict__ out) {
    __shared__ int range[2];
    __shared__ float gs[DIM], ts[DIM];
    int gid = blockIdx.x, t = threadIdx.x;
    if (t < 2) range[t] = lbound(n2g, NN, gid + t);
    __syncthreads();
    int s = range[0], e = range[1];

    float sc = g_bnp[t], sh = g_bnp[DIM + t];
    float sum = 0.f;
    for (int n = s; n < e; n++)
        sum += fmaxf(fmaf(yin[(size_t)n * DIM + t], sc, sh), 0.f);
    float cnt = fmaxf((float)(e - s), 1.0f);
    gs[t] = sum / cnt;
    __syncthreads();

    float acc = b1[t];
#pragma unroll 4
    for (int k = 0; k < DIM; k++) acc = fmaf(gs[k], W1[k * DIM + t], acc);
    ts[t] = fmaxf(acc, 0.f);
    __syncthreads();
    float acc2 = b2[t];
#pragma unroll 4
    for (int k = 0; k < DIM; k++) acc2 = fmaf(ts[k], W2[k * DIM + t], acc2);
    out[gid * DIM + t] = acc2;
}

// ---------------- launcher ----------------
extern "C" void kernel_launch(void* const* d_in, const int* in_sizes, int n_in,
                              void* d_out, int out_size) {
    const int*   nfeat    = (const int*)d_in[0];
    const int*   efeat    = (const int*)d_in[1];
    const int*   src      = (const int*)d_in[2];
    const int*   dst      = (const int*)d_in[3];
    const int*   n2g      = (const int*)d_in[4];
    const float* atom_emb = (const float*)d_in[5];
    const float* edge_emb = (const float*)d_in[6];
    const float* W        = (const float*)d_in[7];
    const float* b        = (const float*)d_in[8];
    const float* gamma    = (const float*)d_in[9];
    const float* beta     = (const float*)d_in[10];
    const float* W1       = (const float*)d_in[11];
    const float* b1       = (const float*)d_in[12];
    const float* W2       = (const float*)d_in[13];
    const float* b2       = (const float*)d_in[14];
    float* out = (float*)d_out;

    static bool attr_set = false;
    if (!attr_set) {
        cudaFuncSetAttribute(k_layer<false>,
                             cudaFuncAttributeMaxDynamicSharedMemorySize, SM_TOTAL);
        cudaFuncSetAttribute(k_layer<true>,
                             cudaFuncAttributeMaxDynamicSharedMemorySize, SM_TOTAL);
        attr_set = true;
    }

    const int nthr = 256;
    int gNode32 = (NN * 32 + nthr - 1) / nthr;
    int gEdge   = (NE + nthr - 1) / nthr;
    int gNode   = (NN + nthr - 1) / nthr;

    k_init<<<gNode32, nthr>>>(nfeat, atom_emb);
    k_hist<<<gEdge, nthr>>>(dst);
    k_wconv<<<NL, 128>>>(W);
    k_scan1<<<NBLK, 256>>>();
    k_scan2<<<1, 1024>>>();
    k_scan3<<<gNode, nthr>>>();
    k_fill<<<gEdge, nthr>>>(src, dst, efeat);

    float* ybuf0 = nullptr;
    cudaGetSymbolAddress((void**)&ybuf0, g_y);

    for (int l = 0; l < NL; l++) {
        float* yin  = ybuf0 + (size_t)(l & 1) * NN * DIM;
        float* yout = ybuf0 + (size_t)((l & 1) ^ 1) * NN * DIM;
        if (l == 0)
            k_layer<false><<<NTILE, 256, SM_TOTAL>>>(l, edge_emb,
                                                     b + (size_t)l * DIM, yin, yout);
        else
            k_layer<true><<<NTILE, 256, SM_TOTAL>>>(l, edge_emb + (size_t)l * BONDV * DIM,
                                                    b + (size_t)l * DIM, yin, yout);
        k_bnstat<<<1, 128>>>(gamma + (size_t)l * DIM, beta + (size_t)l * DIM);
    }

    k_poolmlp<<<NG, 128>>>(n2g, ybuf0 + (size_t)(NL & 1) * NN * DIM,
                           W1, b1, W2, b2, out);
}

// round 7
// speedup vs baseline: 1.7981x; 1.7981x over previous
#include <cuda_runtime.h>
#include <cuda_bf16.h>
#include <cstdint>

#define NN   200000
#define NE   400000
#define DIM  128
#define NL   5
#define NG   1000
#define BONDV 5
#define NBLK 782           // ceil(NN/256)
#define NTILE 1563         // ceil(NN/128)
#define ROW_BYTES 256      // 128 bf16 per row
#define IMG_BYTES ((size_t)NTILE * 128 * ROW_BYTES)

// ---------------- device scratch ----------------
__device__ float g_y[NN * DIM];       // layer output (pre-BN); also holds h0
__device__ float g_deg[NN];
__device__ float g_stats[2 * DIM];    // column sum / sumsq (self-rezeroing)
__device__ float g_bnp[2 * DIM];      // BN scale / shift
__device__ int   g_cnti[NN];
__device__ int   g_off[NN + 1];
__device__ int   g_cur[NN];
__device__ int   g_blk[NBLK];
__device__ int   g_edge[NE];          // packed (src<<3)|efeat
// bf16-split operands, row-major [row][k] bf16 (pad rows stay zero)
__device__ unsigned char g_ah[IMG_BYTES];
__device__ unsigned char g_al[IMG_BYTES];
__device__ unsigned char g_wh[NL * DIM * ROW_BYTES];  // W^T: [n][k]
__device__ unsigned char g_wl[NL * DIM * ROW_BYTES];

// bf16 hi/lo split of a float pair, packed (low half = first element)
__device__ __forceinline__ void bsplit(float a, float b, uint32_t& hi, uint32_t& lo) {
    __nv_bfloat162 h = __float22bfloat162_rn(make_float2(a, b));
    float2 hf = __bfloat1622float2(h);
    __nv_bfloat162 l = __float22bfloat162_rn(make_float2(a - hf.x, b - hf.y));
    hi = *(uint32_t*)&h;
    lo = *(uint32_t*)&l;
}

__device__ __forceinline__ uint32_t smem_u32(const void* p) {
    uint32_t a;
    asm("{ .reg .u64 t; cvta.to.shared.u64 t, %1; cvt.u32.u64 %0, t; }"
        : "=r"(a) : "l"(p));
    return a;
}
__device__ __forceinline__ void ldsm4(uint32_t& r0, uint32_t& r1, uint32_t& r2,
                                      uint32_t& r3, uint32_t addr) {
    asm volatile("ldmatrix.sync.aligned.m8n8.x4.shared.b16 {%0,%1,%2,%3}, [%4];"
                 : "=r"(r0), "=r"(r1), "=r"(r2), "=r"(r3) : "r"(addr));
}
__device__ __forceinline__ void mma16816(float* d, uint32_t a0, uint32_t a1,
                                         uint32_t a2, uint32_t a3,
                                         uint32_t b0, uint32_t b1) {
    asm volatile(
        "mma.sync.aligned.m16n8k16.row.col.f32.bf16.bf16.f32 "
        "{%0,%1,%2,%3}, {%4,%5,%6,%7}, {%8,%9}, {%0,%1,%2,%3};"
        : "+f"(d[0]), "+f"(d[1]), "+f"(d[2]), "+f"(d[3])
        : "r"(a0), "r"(a1), "r"(a2), "r"(a3), "r"(b0), "r"(b1));
}

// ---------------- setup kernels ----------------
__global__ void k_init(const int* __restrict__ nfeat,
                       const float* __restrict__ atom_emb) {
    int idx = blockIdx.x * blockDim.x + threadIdx.x;
    if (idx >= NN * 32) return;
    int node = idx >> 5, c = idx & 31;
    int a = nfeat[node];
    ((float4*)g_y)[node * 32 + c] = ((const float4*)atom_emb)[a * 32 + c];
    if (c == 0) g_cnti[node] = 0;
}

__global__ void k_hist(const int* __restrict__ dst) {
    int e = blockIdx.x * blockDim.x + threadIdx.x;
    if (e < NE) atomicAdd(&g_cnti[dst[e]], 1);
}

__global__ void k_scan1() {
    __shared__ int s[256];
    int i = blockIdx.x * 256 + threadIdx.x;
    int c = (i < NN) ? g_cnti[i] : 0;
    s[threadIdx.x] = c;
    __syncthreads();
    int v = c;
#pragma unroll
    for (int d = 1; d < 256; d <<= 1) {
        int t = (threadIdx.x >= d) ? s[threadIdx.x - d] : 0;
        __syncthreads();
        v += t;
        s[threadIdx.x] = v;
        __syncthreads();
    }
    if (i < NN) g_off[i] = v - c;
    if (threadIdx.x == 255) g_blk[blockIdx.x] = v;
}

__global__ void k_scan2() {
    __shared__ int s[1024];
    int t = threadIdx.x;
    int c = (t < NBLK) ? g_blk[t] : 0;
    s[t] = c;
    __syncthreads();
    int v = c;
#pragma unroll
    for (int d = 1; d < 1024; d <<= 1) {
        int x = (t >= d) ? s[t - d] : 0;
        __syncthreads();
        v += x;
        s[t] = v;
        __syncthreads();
    }
    if (t < NBLK) g_blk[t] = v - c;
}

__global__ void k_scan3() {
    int i = blockIdx.x * blockDim.x + threadIdx.x;
    if (i >= NN) return;
    int off = g_off[i] + g_blk[i >> 8];
    g_off[i] = off;
    g_cur[i] = off;
    g_deg[i] = 1.0f / (float)(g_cnti[i] + 1);
    if (i == 0) g_off[NN] = NE;
}

__global__ void k_fill(const int* __restrict__ src, const int* __restrict__ dst,
                       const int* __restrict__ efeat) {
    int e = blockIdx.x * blockDim.x + threadIdx.x;
    if (e >= NE) return;
    int d = dst[e];
    int pos = atomicAdd(&g_cur[d], 1);
    g_edge[pos] = (src[e] << 3) | efeat[e];
}

// W^T images: BT[n][k] = W[k][n], bf16 hi/lo row-major
__global__ void k_wconv(const float* __restrict__ W) {
    int l = blockIdx.x, t = threadIdx.x;  // t = n
    const float* Wl = W + (size_t)l * DIM * DIM;
    unsigned char* wh = g_wh + (size_t)l * DIM * ROW_BYTES;
    unsigned char* wl = g_wl + (size_t)l * DIM * ROW_BYTES;
    for (int k = 0; k < DIM; k += 2) {
        uint32_t hi, lo;
        bsplit(Wl[k * DIM + t], Wl[(k + 1) * DIM + t], hi, lo);
        uint32_t byte = (uint32_t)(t * ROW_BYTES + k * 2);
        *(uint32_t*)(wh + byte) = hi;
        *(uint32_t*)(wl + byte) = lo;
    }
}

// ---------------- per-layer kernels ----------------

// A row = (h[n] + sum_in (h[src]+eemb[f])) * deg_inv, h = BN? relu(y*sc+sh) : y
// output: bf16 hi/lo row-major
template <bool BN>
__global__ void __launch_bounds__(256) k_aggregate(const float* __restrict__ eembL) {
    __shared__ float se[BONDV * DIM];
    int tid = threadIdx.x;
    if (tid < BONDV * 32)
        ((float4*)se)[tid] = ((const float4*)eembL)[tid];
    __syncthreads();

    int n = blockIdx.x * 8 + (tid >> 5);
    if (n >= NN) return;
    int c = tid & 31;

    float4 sc, sh;
    if (BN) {
        sc = ((const float4*)g_bnp)[c];
        sh = ((const float4*)(g_bnp + DIM))[c];
    }

    const float4* y4 = (const float4*)g_y;
    const float4* se4 = (const float4*)se;

    float4 acc;
    {
        float4 v = y4[n * 32 + c];
        if (BN) {
            acc.x = fmaxf(fmaf(v.x, sc.x, sh.x), 0.f);
            acc.y = fmaxf(fmaf(v.y, sc.y, sh.y), 0.f);
            acc.z = fmaxf(fmaf(v.z, sc.z, sh.z), 0.f);
            acc.w = fmaxf(fmaf(v.w, sc.w, sh.w), 0.f);
        } else acc = v;
    }

    int p0 = g_off[n], p1 = g_off[n + 1];
    for (int p = p0; p < p1; p++) {
        int pk = g_edge[p];
        int s = pk >> 3, f = pk & 7;
        float4 v = y4[s * 32 + c];
        float4 ev = se4[f * 32 + c];
        if (BN) {
            acc.x += fmaxf(fmaf(v.x, sc.x, sh.x), 0.f) + ev.x;
            acc.y += fmaxf(fmaf(v.y, sc.y, sh.y), 0.f) + ev.y;
            acc.z += fmaxf(fmaf(v.z, sc.z, sh.z), 0.f) + ev.z;
            acc.w += fmaxf(fmaf(v.w, sc.w, sh.w), 0.f) + ev.w;
        } else {
            acc.x += v.x + ev.x;
            acc.y += v.y + ev.y;
            acc.z += v.z + ev.z;
            acc.w += v.w + ev.w;
        }
    }
    float dinv = g_deg[n];
    acc.x *= dinv; acc.y *= dinv; acc.z *= dinv; acc.w *= dinv;

    uint2 hi2, lo2;
    bsplit(acc.x, acc.y, hi2.x, lo2.x);
    bsplit(acc.z, acc.w, hi2.y, lo2.y);
    size_t base = (size_t)n * ROW_BYTES + c * 8;
    *(uint2*)(g_ah + base) = hi2;
    *(uint2*)(g_al + base) = lo2;
}

// ---- tensor-core GEMM via mma.sync bf16 3-term split: y = A@W + b + stats --
// K split into two 64-wide halves staged into the SAME smem buffers:
// smem = 73.5 KB -> 2 CTAs/SM, staging of one CTA overlaps MMA of the other.
#define PITCH2 144                // 64 bf16 (128B) rows padded to 9x16B
#define HIMG (128 * PITCH2)       // 18432 bytes per half-image
#define SM_BIAS 0
#define SM_SUM  512
#define SM_SQ   1024
#define SM_AH   1536
#define SM_AL   (SM_AH + HIMG)
#define SM_WH   (SM_AL + HIMG)
#define SM_WL   (SM_WH + HIMG)
#define SM_TOTAL (SM_WL + HIMG)   // 75264

__global__ void __launch_bounds__(256, 2) k_gemm(int layer, const float* __restrict__ bl) {
    extern __shared__ char smem[];
    uint32_t sb = smem_u32(smem);
    int tid = threadIdx.x, wid = tid >> 5, lane = tid & 31;
    int g = lane >> 2, tg = lane & 3;

    float* sbias = (float*)(smem + SM_BIAS);
    float* ssum  = (float*)(smem + SM_SUM);
    float* ssq   = (float*)(smem + SM_SQ);
    if (tid < 128) {
        sbias[tid] = bl[tid];
        ssum[tid] = 0.f;
        ssq[tid] = 0.f;
    }

    const float4* gah = (const float4*)(g_ah + (size_t)blockIdx.x * 128 * ROW_BYTES);
    const float4* gal = (const float4*)(g_al + (size_t)blockIdx.x * 128 * ROW_BYTES);
    const float4* gwh = (const float4*)(g_wh + (size_t)layer * DIM * ROW_BYTES);
    const float4* gwl = (const float4*)(g_wl + (size_t)layer * DIM * ROW_BYTES);

    // per-lane ldmatrix address components (pitch PITCH2)
    uint32_t a_row = 16 * wid + (lane & 15);
    uint32_t a_kof = (lane >> 4) * 16;
    uint32_t ah_base = sb + SM_AH + a_row * PITCH2 + a_kof;
    uint32_t al_base = sb + SM_AL + a_row * PITCH2 + a_kof;
    uint32_t b_row = ((lane >> 4) << 3) + (lane & 7);
    uint32_t b_kof = ((lane >> 3) & 1) * 16;
    uint32_t wh_base = sb + SM_WH + b_row * PITCH2 + b_kof;
    uint32_t wl_base = sb + SM_WL + b_row * PITCH2 + b_kof;

    float d[16][4];
#pragma unroll
    for (int i = 0; i < 16; i++)
#pragma unroll
        for (int j = 0; j < 4; j++) d[i][j] = 0.f;

#pragma unroll
    for (int kh = 0; kh < 2; kh++) {
        // stage this k-half: 1024 float4 per image, 4 per thread
#pragma unroll
        for (int i = 0; i < 4; i++) {
            int idx = tid + i * 256;          // 0..1023
            int row = idx >> 3, q = idx & 7;  // 8 float4 per half-row
            int gidx = row * 16 + kh * 8 + q; // global: 16 float4 per full row
            int soff = row * (PITCH2 / 16) + q;
            ((float4*)(smem + SM_AH))[soff] = gah[gidx];
            ((float4*)(smem + SM_AL))[soff] = gal[gidx];
            ((float4*)(smem + SM_WH))[soff] = gwh[gidx];
            ((float4*)(smem + SM_WL))[soff] = gwl[gidx];
        }
        __syncthreads();

#pragma unroll
        for (int ks = 0; ks < 4; ks++) {
            uint32_t ah0, ah1, ah2, ah3, al0, al1, al2, al3;
            ldsm4(ah0, ah1, ah2, ah3, ah_base + ks * 32);
            ldsm4(al0, al1, al2, al3, al_base + ks * 32);
#pragma unroll
            for (int nt2 = 0; nt2 < 8; nt2++) {
                uint32_t bh0, bh1, bh2, bh3, bl0_, bl1_, bl2_, bl3_;
                uint32_t off = nt2 * 16 * PITCH2 + ks * 32;
                ldsm4(bh0, bh1, bh2, bh3, wh_base + off);
                ldsm4(bl0_, bl1_, bl2_, bl3_, wl_base + off);
                mma16816(d[2 * nt2], ah0, ah1, ah2, ah3, bh0, bh1);
                mma16816(d[2 * nt2], al0, al1, al2, al3, bh0, bh1);
                mma16816(d[2 * nt2], ah0, ah1, ah2, ah3, bl0_, bl1_);
                mma16816(d[2 * nt2 + 1], ah0, ah1, ah2, ah3, bh2, bh3);
                mma16816(d[2 * nt2 + 1], al0, al1, al2, al3, bh2, bh3);
                mma16816(d[2 * nt2 + 1], ah0, ah1, ah2, ah3, bl2_, bl3_);
            }
        }
        __syncthreads();   // buffers reused by next half
    }

    // epilogue: bias, masked store, column stats
    int row0 = blockIdx.x * 128 + 16 * wid + g;
    int row1 = row0 + 8;
    bool v0 = row0 < NN, v1 = row1 < NN;

#pragma unroll
    for (int nt = 0; nt < 16; nt++) {
        int c0 = nt * 8 + 2 * tg;
        float b0 = sbias[c0], b1 = sbias[c0 + 1];
        float y0 = d[nt][0] + b0, y1 = d[nt][1] + b1;
        float y2 = d[nt][2] + b0, y3 = d[nt][3] + b1;
        if (!v0) { y0 = 0.f; y1 = 0.f; }
        if (!v1) { y2 = 0.f; y3 = 0.f; }
        if (v0) *(float2*)&g_y[(size_t)row0 * DIM + c0] = make_float2(y0, y1);
        if (v1) *(float2*)&g_y[(size_t)row1 * DIM + c0] = make_float2(y2, y3);

        float s0 = y0 + y2, s1 = y1 + y3;
        float q0 = y0 * y0 + y2 * y2, q1 = y1 * y1 + y3 * y3;
#pragma unroll
        for (int m = 4; m <= 16; m <<= 1) {
            s0 += __shfl_xor_sync(0xffffffffu, s0, m);
            s1 += __shfl_xor_sync(0xffffffffu, s1, m);
            q0 += __shfl_xor_sync(0xffffffffu, q0, m);
            q1 += __shfl_xor_sync(0xffffffffu, q1, m);
        }
        if (lane < 4) {
            atomicAdd(&ssum[c0], s0);
            atomicAdd(&ssum[c0 + 1], s1);
            atomicAdd(&ssq[c0], q0);
            atomicAdd(&ssq[c0 + 1], q1);
        }
    }
    __syncthreads();
    if (tid < 128) {
        atomicAdd(&g_stats[tid], ssum[tid]);
        atomicAdd(&g_stats[DIM + tid], ssq[tid]);
    }
}

// finalize BN params; re-zero stats (replay-safe)
__global__ void k_bnstat(const float* __restrict__ gammaL,
                         const float* __restrict__ betaL) {
    int t = threadIdx.x;  // 128
    float mu  = g_stats[t] * (1.0f / NN);
    float var = g_stats[DIM + t] * (1.0f / NN) - mu * mu;
    float rstd = rsqrtf(var + 1e-5f);
    float sc = rstd * gammaL[t];
    g_bnp[t] = sc;
    g_bnp[DIM + t] = betaL[t] - mu * sc;
    g_stats[t] = 0.f;
    g_stats[DIM + t] = 0.f;
}

// ---------------- fused pool + MLP (n2g sorted); applies final BN+relu ------
__device__ __forceinline__ int lbound(const int* __restrict__ a, int n, int key) {
    int lo = 0, hi = n;
    while (lo < hi) {
        int mid = (lo + hi) >> 1;
        if (a[mid] < key) lo = mid + 1; else hi = mid;
    }
    return lo;
}

__global__ void __launch_bounds__(128) k_poolmlp(const int* __restrict__ n2g,
                                                 const float* __restrict__ W1,
                                                 const float* __restrict__ b1,
                                                 const float* __restrict__ W2,
                                                 const float* __restrict__ b2,
                                                 float* __restrict__ out) {
    __shared__ int range[2];
    __shared__ float gs[DIM], ts[DIM];
    int gid = blockIdx.x, t = threadIdx.x;
    if (t < 2) range[t] = lbound(n2g, NN, gid + t);
    __syncthreads();
    int s = range[0], e = range[1];

    float sc = g_bnp[t], sh = g_bnp[DIM + t];
    float sum = 0.f;
    for (int n = s; n < e; n++)
        sum += fmaxf(fmaf(g_y[(size_t)n * DIM + t], sc, sh), 0.f);
    float cnt = fmaxf((float)(e - s), 1.0f);
    gs[t] = sum / cnt;
    __syncthreads();

    float acc = b1[t];
#pragma unroll 4
    for (int k = 0; k < DIM; k++) acc = fmaf(gs[k], W1[k * DIM + t], acc);
    ts[t] = fmaxf(acc, 0.f);
    __syncthreads();
    float acc2 = b2[t];
#pragma unroll 4
    for (int k = 0; k < DIM; k++) acc2 = fmaf(ts[k], W2[k * DIM + t], acc2);
    out[gid * DIM + t] = acc2;
}

// ---------------- launcher ----------------
extern "C" void kernel_launch(void* const* d_in, const int* in_sizes, int n_in,
                              void* d_out, int out_size) {
    const int*   nfeat    = (const int*)d_in[0];
    const int*   efeat    = (const int*)d_in[1];
    const int*   src      = (const int*)d_in[2];
    const int*   dst      = (const int*)d_in[3];
    const int*   n2g      = (const int*)d_in[4];
    const float* atom_emb = (const float*)d_in[5];
    const float* edge_emb = (const float*)d_in[6];
    const float* W        = (const float*)d_in[7];
    const float* b        = (const float*)d_in[8];
    const float* gamma    = (const float*)d_in[9];
    const float* beta     = (const float*)d_in[10];
    const float* W1       = (const float*)d_in[11];
    const float* b1       = (const float*)d_in[12];
    const float* W2       = (const float*)d_in[13];
    const float* b2       = (const float*)d_in[14];
    float* out = (float*)d_out;

    static bool attr_set = false;
    if (!attr_set) {
        cudaFuncSetAttribute(k_gemm, cudaFuncAttributeMaxDynamicSharedMemorySize,
                             SM_TOTAL);
        attr_set = true;
    }

    const int nthr = 256;
    int gNode32 = (NN * 32 + nthr - 1) / nthr;
    int gEdge   = (NE + nthr - 1) / nthr;
    int gNode   = (NN + nthr - 1) / nthr;

    k_init<<<gNode32, nthr>>>(nfeat, atom_emb);
    k_hist<<<gEdge, nthr>>>(dst);
    k_wconv<<<NL, 128>>>(W);
    k_scan1<<<NBLK, 256>>>();
    k_scan2<<<1, 1024>>>();
    k_scan3<<<gNode, nthr>>>();
    k_fill<<<gEdge, nthr>>>(src, dst, efeat);

    for (int l = 0; l < NL; l++) {
        if (l == 0)
            k_aggregate<false><<<(NN + 7) / 8, 256>>>(edge_emb);
        else
            k_aggregate<true><<<(NN + 7) / 8, 256>>>(edge_emb + (size_t)l * BONDV * DIM);
        k_gemm<<<NTILE, 256, SM_TOTAL>>>(l, b + (size_t)l * DIM);
        k_bnstat<<<1, 128>>>(gamma + (size_t)l * DIM, beta + (size_t)l * DIM);
    }

    k_poolmlp<<<NG, 128>>>(n2g, W1, b1, W2, b2, out);
}

// round 8
// speedup vs baseline: 1.8011x; 1.0017x over previous
#include <cuda_runtime.h>
#include <cuda_bf16.h>
#include <cstdint>

#define NN   200000
#define NE   400000
#define DIM  128
#define NL   5
#define NG   1000
#define BONDV 5
#define NBLK 782           // ceil(NN/256)
#define NTILE 1563         // ceil(NN/128)
#define ROW_BYTES 256      // 128 bf16 per row
#define IMG_BYTES ((size_t)NTILE * 128 * ROW_BYTES)

// ---------------- device scratch ----------------
__device__ float g_y[NN * DIM];          // layer output (pre-BN); also holds h0
__device__ float g_deg[NN];
__device__ float g_statsL[NL * 2 * DIM]; // per-layer column sum / sumsq
__device__ int   g_cnti[NN];
__device__ int   g_off[NN + 1];
__device__ int   g_cur[NN];
__device__ int   g_blk[NBLK];
__device__ int   g_edge[NE];             // packed (src<<3)|efeat
// bf16-split operands, row-major [row][k] bf16 (pad rows stay zero)
__device__ unsigned char g_ah[IMG_BYTES];
__device__ unsigned char g_al[IMG_BYTES];
__device__ unsigned char g_wh[NL * DIM * ROW_BYTES];  // W^T: [n][k]
__device__ unsigned char g_wl[NL * DIM * ROW_BYTES];

// bf16 hi/lo split of a float pair, packed (low half = first element)
__device__ __forceinline__ void bsplit(float a, float b, uint32_t& hi, uint32_t& lo) {
    __nv_bfloat162 h = __float22bfloat162_rn(make_float2(a, b));
    float2 hf = __bfloat1622float2(h);
    __nv_bfloat162 l = __float22bfloat162_rn(make_float2(a - hf.x, b - hf.y));
    hi = *(uint32_t*)&h;
    lo = *(uint32_t*)&l;
}

__device__ __forceinline__ uint32_t smem_u32(const void* p) {
    uint32_t a;
    asm("{ .reg .u64 t; cvta.to.shared.u64 t, %1; cvt.u32.u64 %0, t; }"
        : "=r"(a) : "l"(p));
    return a;
}
__device__ __forceinline__ void ldsm4(uint32_t& r0, uint32_t& r1, uint32_t& r2,
                                      uint32_t& r3, uint32_t addr) {
    asm volatile("ldmatrix.sync.aligned.m8n8.x4.shared.b16 {%0,%1,%2,%3}, [%4];"
                 : "=r"(r0), "=r"(r1), "=r"(r2), "=r"(r3) : "r"(addr));
}
__device__ __forceinline__ void mma16816(float* d, uint32_t a0, uint32_t a1,
                                         uint32_t a2, uint32_t a3,
                                         uint32_t b0, uint32_t b1) {
    asm volatile(
        "mma.sync.aligned.m16n8k16.row.col.f32.bf16.bf16.f32 "
        "{%0,%1,%2,%3}, {%4,%5,%6,%7}, {%8,%9}, {%0,%1,%2,%3};"
        : "+f"(d[0]), "+f"(d[1]), "+f"(d[2]), "+f"(d[3])
        : "r"(a0), "r"(a1), "r"(a2), "r"(a3), "r"(b0), "r"(b1));
}
__device__ __forceinline__ void cpasync16(uint32_t saddr, const void* g) {
    asm volatile("cp.async.cg.shared.global [%0], [%1], 16;"
                 :: "r"(saddr), "l"(g) : "memory");
}

// ---------------- setup kernels ----------------
__global__ void k_init(const int* __restrict__ nfeat,
                       const float* __restrict__ atom_emb) {
    int idx = blockIdx.x * blockDim.x + threadIdx.x;
    if (idx < NL * 2 * DIM) g_statsL[idx] = 0.f;   // replay-safe stats re-zero
    if (idx >= NN * 32) return;
    int node = idx >> 5, c = idx & 31;
    int a = nfeat[node];
    ((float4*)g_y)[node * 32 + c] = ((const float4*)atom_emb)[a * 32 + c];
    if (c == 0) g_cnti[node] = 0;
}

__global__ void k_hist(const int* __restrict__ dst) {
    int e = blockIdx.x * blockDim.x + threadIdx.x;
    if (e < NE) atomicAdd(&g_cnti[dst[e]], 1);
}

__global__ void k_scan1() {
    __shared__ int s[256];
    int i = blockIdx.x * 256 + threadIdx.x;
    int c = (i < NN) ? g_cnti[i] : 0;
    s[threadIdx.x] = c;
    __syncthreads();
    int v = c;
#pragma unroll
    for (int d = 1; d < 256; d <<= 1) {
        int t = (threadIdx.x >= d) ? s[threadIdx.x - d] : 0;
        __syncthreads();
        v += t;
        s[threadIdx.x] = v;
        __syncthreads();
    }
    if (i < NN) g_off[i] = v - c;
    if (threadIdx.x == 255) g_blk[blockIdx.x] = v;
}

__global__ void k_scan2() {
    __shared__ int s[1024];
    int t = threadIdx.x;
    int c = (t < NBLK) ? g_blk[t] : 0;
    s[t] = c;
    __syncthreads();
    int v = c;
#pragma unroll
    for (int d = 1; d < 1024; d <<= 1) {
        int x = (t >= d) ? s[t - d] : 0;
        __syncthreads();
        v += x;
        s[t] = v;
        __syncthreads();
    }
    if (t < NBLK) g_blk[t] = v - c;
}

__global__ void k_scan3() {
    int i = blockIdx.x * blockDim.x + threadIdx.x;
    if (i >= NN) return;
    int off = g_off[i] + g_blk[i >> 8];
    g_off[i] = off;
    g_cur[i] = off;
    g_deg[i] = 1.0f / (float)(g_cnti[i] + 1);
    if (i == 0) g_off[NN] = NE;
}

__global__ void k_fill(const int* __restrict__ src, const int* __restrict__ dst,
                       const int* __restrict__ efeat) {
    int e = blockIdx.x * blockDim.x + threadIdx.x;
    if (e >= NE) return;
    int d = dst[e];
    int pos = atomicAdd(&g_cur[d], 1);
    g_edge[pos] = (src[e] << 3) | efeat[e];
}

// W^T images: BT[n][k] = W[k][n], bf16 hi/lo row-major
__global__ void k_wconv(const float* __restrict__ W) {
    int l = blockIdx.x, t = threadIdx.x;  // t = n
    const float* Wl = W + (size_t)l * DIM * DIM;
    unsigned char* wh = g_wh + (size_t)l * DIM * ROW_BYTES;
    unsigned char* wl = g_wl + (size_t)l * DIM * ROW_BYTES;
    for (int k = 0; k < DIM; k += 2) {
        uint32_t hi, lo;
        bsplit(Wl[k * DIM + t], Wl[(k + 1) * DIM + t], hi, lo);
        uint32_t byte = (uint32_t)(t * ROW_BYTES + k * 2);
        *(uint32_t*)(wh + byte) = hi;
        *(uint32_t*)(wl + byte) = lo;
    }
}

// ---------------- per-layer kernels ----------------

// A row = (h[n] + sum_in (h[src]+eemb[f])) * deg_inv, h = BN? relu(y*sc+sh) : y
// BN params computed inline from the previous layer's stats (no bnstat kernel).
template <bool BN>
__global__ void __launch_bounds__(256) k_aggregate(const float* __restrict__ eembL,
                                                   const float* __restrict__ stats,
                                                   const float* __restrict__ gammaL,
                                                   const float* __restrict__ betaL) {
    __shared__ float se[BONDV * DIM];
    __shared__ float sbnp[2 * DIM];
    int tid = threadIdx.x;
    if (tid < BONDV * 32)
        ((float4*)se)[tid] = ((const float4*)eembL)[tid];
    if (BN && tid < DIM) {
        float mu  = stats[tid] * (1.0f / NN);
        float var = stats[DIM + tid] * (1.0f / NN) - mu * mu;
        float rstd = rsqrtf(var + 1e-5f);
        float sc = rstd * gammaL[tid];
        sbnp[tid] = sc;
        sbnp[DIM + tid] = betaL[tid] - mu * sc;
    }
    __syncthreads();

    int n = blockIdx.x * 8 + (tid >> 5);
    if (n >= NN) return;
    int c = tid & 31;

    float4 sc, sh;
    if (BN) {
        sc = ((const float4*)sbnp)[c];
        sh = ((const float4*)(sbnp + DIM))[c];
    }

    const float4* y4 = (const float4*)g_y;
    const float4* se4 = (const float4*)se;

    float4 acc;
    {
        float4 v = y4[n * 32 + c];
        if (BN) {
            acc.x = fmaxf(fmaf(v.x, sc.x, sh.x), 0.f);
            acc.y = fmaxf(fmaf(v.y, sc.y, sh.y), 0.f);
            acc.z = fmaxf(fmaf(v.z, sc.z, sh.z), 0.f);
            acc.w = fmaxf(fmaf(v.w, sc.w, sh.w), 0.f);
        } else acc = v;
    }

    int p0 = g_off[n], p1 = g_off[n + 1];
    for (int p = p0; p < p1; p++) {
        int pk = g_edge[p];
        int s = pk >> 3, f = pk & 7;
        float4 v = y4[s * 32 + c];
        float4 ev = se4[f * 32 + c];
        if (BN) {
            acc.x += fmaxf(fmaf(v.x, sc.x, sh.x), 0.f) + ev.x;
            acc.y += fmaxf(fmaf(v.y, sc.y, sh.y), 0.f) + ev.y;
            acc.z += fmaxf(fmaf(v.z, sc.z, sh.z), 0.f) + ev.z;
            acc.w += fmaxf(fmaf(v.w, sc.w, sh.w), 0.f) + ev.w;
        } else {
            acc.x += v.x + ev.x;
            acc.y += v.y + ev.y;
            acc.z += v.z + ev.z;
            acc.w += v.w + ev.w;
        }
    }
    float dinv = g_deg[n];
    acc.x *= dinv; acc.y *= dinv; acc.z *= dinv; acc.w *= dinv;

    uint2 hi2, lo2;
    bsplit(acc.x, acc.y, hi2.x, lo2.x);
    bsplit(acc.z, acc.w, hi2.y, lo2.y);
    size_t base = (size_t)n * ROW_BYTES + c * 8;
    *(uint2*)(g_ah + base) = hi2;
    *(uint2*)(g_al + base) = lo2;
}

// ---- tensor-core GEMM via mma.sync bf16 3-term split: y = A@W + b + stats --
// K split into two 64-wide halves staged (cp.async) into the SAME smem buffers:
// smem = 73.5 KB -> 2 CTAs/SM.
#define PITCH2 144                // 64 bf16 (128B) rows padded to 9x16B
#define HIMG (128 * PITCH2)       // 18432 bytes per half-image
#define SM_BIAS 0
#define SM_SUM  512
#define SM_SQ   1024
#define SM_AH   1536
#define SM_AL   (SM_AH + HIMG)
#define SM_WH   (SM_AL + HIMG)
#define SM_WL   (SM_WH + HIMG)
#define SM_TOTAL (SM_WL + HIMG)   // 75264

__global__ void __launch_bounds__(256, 2) k_gemm(int layer, const float* __restrict__ bl) {
    extern __shared__ char smem[];
    uint32_t sb = smem_u32(smem);
    int tid = threadIdx.x, wid = tid >> 5, lane = tid & 31;
    int g = lane >> 2, tg = lane & 3;

    float* sbias = (float*)(smem + SM_BIAS);
    float* ssum  = (float*)(smem + SM_SUM);
    float* ssq   = (float*)(smem + SM_SQ);
    if (tid < 128) {
        sbias[tid] = bl[tid];
        ssum[tid] = 0.f;
        ssq[tid] = 0.f;
    }

    const float4* gah = (const float4*)(g_ah + (size_t)blockIdx.x * 128 * ROW_BYTES);
    const float4* gal = (const float4*)(g_al + (size_t)blockIdx.x * 128 * ROW_BYTES);
    const float4* gwh = (const float4*)(g_wh + (size_t)layer * DIM * ROW_BYTES);
    const float4* gwl = (const float4*)(g_wl + (size_t)layer * DIM * ROW_BYTES);

    // per-lane ldmatrix address components (pitch PITCH2)
    uint32_t a_row = 16 * wid + (lane & 15);
    uint32_t a_kof = (lane >> 4) * 16;
    uint32_t ah_base = sb + SM_AH + a_row * PITCH2 + a_kof;
    uint32_t al_base = sb + SM_AL + a_row * PITCH2 + a_kof;
    uint32_t b_row = ((lane >> 4) << 3) + (lane & 7);
    uint32_t b_kof = ((lane >> 3) & 1) * 16;
    uint32_t wh_base = sb + SM_WH + b_row * PITCH2 + b_kof;
    uint32_t wl_base = sb + SM_WL + b_row * PITCH2 + b_kof;

    float d[16][4];
#pragma unroll
    for (int i = 0; i < 16; i++)
#pragma unroll
        for (int j = 0; j < 4; j++) d[i][j] = 0.f;

#pragma unroll
    for (int kh = 0; kh < 2; kh++) {
        // stage this k-half via cp.async: 1024 float4 per image, 4 per thread
#pragma unroll
        for (int i = 0; i < 4; i++) {
            int idx = tid + i * 256;          // 0..1023
            int row = idx >> 3, q = idx & 7;  // 8 float4 per half-row
            int gidx = row * 16 + kh * 8 + q; // global: 16 float4 per full row
            uint32_t soff = row * PITCH2 + q * 16;
            cpasync16(sb + SM_AH + soff, gah + gidx);
            cpasync16(sb + SM_AL + soff, gal + gidx);
            cpasync16(sb + SM_WH + soff, gwh + gidx);
            cpasync16(sb + SM_WL + soff, gwl + gidx);
        }
        asm volatile("cp.async.commit_group;" ::: "memory");
        asm volatile("cp.async.wait_group 0;" ::: "memory");
        __syncthreads();

#pragma unroll
        for (int ks = 0; ks < 4; ks++) {
            uint32_t ah0, ah1, ah2, ah3, al0, al1, al2, al3;
            ldsm4(ah0, ah1, ah2, ah3, ah_base + ks * 32);
            ldsm4(al0, al1, al2, al3, al_base + ks * 32);
#pragma unroll
            for (int nt2 = 0; nt2 < 8; nt2++) {
                uint32_t bh0, bh1, bh2, bh3, bl0_, bl1_, bl2_, bl3_;
                uint32_t off = nt2 * 16 * PITCH2 + ks * 32;
                ldsm4(bh0, bh1, bh2, bh3, wh_base + off);
                ldsm4(bl0_, bl1_, bl2_, bl3_, wl_base + off);
                mma16816(d[2 * nt2], ah0, ah1, ah2, ah3, bh0, bh1);
                mma16816(d[2 * nt2], al0, al1, al2, al3, bh0, bh1);
                mma16816(d[2 * nt2], ah0, ah1, ah2, ah3, bl0_, bl1_);
                mma16816(d[2 * nt2 + 1], ah0, ah1, ah2, ah3, bh2, bh3);
                mma16816(d[2 * nt2 + 1], al0, al1, al2, al3, bh2, bh3);
                mma16816(d[2 * nt2 + 1], ah0, ah1, ah2, ah3, bl2_, bl3_);
            }
        }
        __syncthreads();   // buffers reused by next half
    }

    // epilogue: bias, masked store, column stats
    int row0 = blockIdx.x * 128 + 16 * wid + g;
    int row1 = row0 + 8;
    bool v0 = row0 < NN, v1 = row1 < NN;

#pragma unroll
    for (int nt = 0; nt < 16; nt++) {
        int c0 = nt * 8 + 2 * tg;
        float b0 = sbias[c0], b1 = sbias[c0 + 1];
        float y0 = d[nt][0] + b0, y1 = d[nt][1] + b1;
        float y2 = d[nt][2] + b0, y3 = d[nt][3] + b1;
        if (!v0) { y0 = 0.f; y1 = 0.f; }
        if (!v1) { y2 = 0.f; y3 = 0.f; }
        if (v0) *(float2*)&g_y[(size_t)row0 * DIM + c0] = make_float2(y0, y1);
        if (v1) *(float2*)&g_y[(size_t)row1 * DIM + c0] = make_float2(y2, y3);

        float s0 = y0 + y2, s1 = y1 + y3;
        float q0 = y0 * y0 + y2 * y2, q1 = y1 * y1 + y3 * y3;
#pragma unroll
        for (int m = 4; m <= 16; m <<= 1) {
            s0 += __shfl_xor_sync(0xffffffffu, s0, m);
            s1 += __shfl_xor_sync(0xffffffffu, s1, m);
            q0 += __shfl_xor_sync(0xffffffffu, q0, m);
            q1 += __shfl_xor_sync(0xffffffffu, q1, m);
        }
        if (lane < 4) {
            atomicAdd(&ssum[c0], s0);
            atomicAdd(&ssum[c0 + 1], s1);
            atomicAdd(&ssq[c0], q0);
            atomicAdd(&ssq[c0 + 1], q1);
        }
    }
    __syncthreads();
    if (tid < 128) {
        float* st = g_statsL + layer * 2 * DIM;
        atomicAdd(&st[tid], ssum[tid]);
        atomicAdd(&st[DIM + tid], ssq[tid]);
    }
}

// ---------------- fused pool + MLP (n2g sorted); applies final BN+relu ------
__device__ __forceinline__ int lbound(const int* __restrict__ a, int n, int key) {
    int lo = 0, hi = n;
    while (lo < hi) {
        int mid = (lo + hi) >> 1;
        if (a[mid] < key) lo = mid + 1; else hi = mid;
    }
    return lo;
}

__global__ void __launch_bounds__(128) k_poolmlp(const int* __restrict__ n2g,
                                                 const float* __restrict__ stats,
                                                 const float* __restrict__ gammaL,
                                                 const float* __restrict__ betaL,
                                                 const float* __restrict__ W1,
                                                 const float* __restrict__ b1,
                                                 const float* __restrict__ W2,
                                                 const float* __restrict__ b2,
                                                 float* __restrict__ out) {
    __shared__ int range[2];
    __shared__ float gs[DIM], ts[DIM];
    int gid = blockIdx.x, t = threadIdx.x;
    if (t < 2) range[t] = lbound(n2g, NN, gid + t);
    __syncthreads();
    int s = range[0], e = range[1];

    // inline BN params for the final layer
    float mu  = stats[t] * (1.0f / NN);
    float var = stats[DIM + t] * (1.0f / NN) - mu * mu;
    float rstd = rsqrtf(var + 1e-5f);
    float sc = rstd * gammaL[t];
    float sh = betaL[t] - mu * sc;

    float sum = 0.f;
    for (int n = s; n < e; n++)
        sum += fmaxf(fmaf(g_y[(size_t)n * DIM + t], sc, sh), 0.f);
    float cnt = fmaxf((float)(e - s), 1.0f);
    gs[t] = sum / cnt;
    __syncthreads();

    float acc = b1[t];
#pragma unroll 4
    for (int k = 0; k < DIM; k++) acc = fmaf(gs[k], W1[k * DIM + t], acc);
    ts[t] = fmaxf(acc, 0.f);
    __syncthreads();
    float acc2 = b2[t];
#pragma unroll 4
    for (int k = 0; k < DIM; k++) acc2 = fmaf(ts[k], W2[k * DIM + t], acc2);
    out[gid * DIM + t] = acc2;
}

// ---------------- launcher ----------------
extern "C" void kernel_launch(void* const* d_in, const int* in_sizes, int n_in,
                              void* d_out, int out_size) {
    const int*   nfeat    = (const int*)d_in[0];
    const int*   efeat    = (const int*)d_in[1];
    const int*   src      = (const int*)d_in[2];
    const int*   dst      = (const int*)d_in[3];
    const int*   n2g      = (const int*)d_in[4];
    const float* atom_emb = (const float*)d_in[5];
    const float* edge_emb = (const float*)d_in[6];
    const float* W        = (const float*)d_in[7];
    const float* b        = (const float*)d_in[8];
    const float* gamma    = (const float*)d_in[9];
    const float* beta     = (const float*)d_in[10];
    const float* W1       = (const float*)d_in[11];
    const float* b1       = (const float*)d_in[12];
    const float* W2       = (const float*)d_in[13];
    const float* b2       = (const float*)d_in[14];
    float* out = (float*)d_out;

    static bool attr_set = false;
    if (!attr_set) {
        cudaFuncSetAttribute(k_gemm, cudaFuncAttributeMaxDynamicSharedMemorySize,
                             SM_TOTAL);
        attr_set = true;
    }

    float* statsL = nullptr;
    cudaGetSymbolAddress((void**)&statsL, g_statsL);

    const int nthr = 256;
    int gNode32 = (NN * 32 + nthr - 1) / nthr;
    int gEdge   = (NE + nthr - 1) / nthr;
    int gNode   = (NN + nthr - 1) / nthr;

    k_init<<<gNode32, nthr>>>(nfeat, atom_emb);
    k_hist<<<gEdge, nthr>>>(dst);
    k_wconv<<<NL, 128>>>(W);
    k_scan1<<<NBLK, 256>>>();
    k_scan2<<<1, 1024>>>();
    k_scan3<<<gNode, nthr>>>();
    k_fill<<<gEdge, nthr>>>(src, dst, efeat);

    for (int l = 0; l < NL; l++) {
        if (l == 0)
            k_aggregate<false><<<(NN + 7) / 8, 256>>>(edge_emb, nullptr,
                                                      nullptr, nullptr);
        else
            k_aggregate<true><<<(NN + 7) / 8, 256>>>(
                edge_emb + (size_t)l * BONDV * DIM,
                statsL + (size_t)(l - 1) * 2 * DIM,
                gamma + (size_t)(l - 1) * DIM,
                beta + (size_t)(l - 1) * DIM);
        k_gemm<<<NTILE, 256, SM_TOTAL>>>(l, b + (size_t)l * DIM);
    }

    k_poolmlp<<<NG, 128>>>(n2g,
                           statsL + (size_t)(NL - 1) * 2 * DIM,
                           gamma + (size_t)(NL - 1) * DIM,
                           beta + (size_t)(NL - 1) * DIM,
                           W1, b1, W2, b2, out);
}

// round 9
// speedup vs baseline: 1.8247x; 1.0131x over previous
#include <cuda_runtime.h>
#include <cuda_bf16.h>
#include <cstdint>

#define NN   200000
#define NE   400000
#define DIM  128
#define NL   5
#define NG   1000
#define ATOMV 119
#define BONDV 5
#define NBLK 782           // ceil(NN/256)
#define NTILE 1563         // ceil(NN/128)
#define ROW_BYTES 256      // 128 bf16 per row
#define IMG_BYTES ((size_t)NTILE * 128 * ROW_BYTES)

// ---------------- device scratch ----------------
__device__ float g_y[NN * DIM];          // layer output (pre-BN)
__device__ float g_deg[NN];
__device__ float g_statsL[NL * 2 * DIM]; // per-layer column sum / sumsq
__device__ int   g_cnti[NN];
__device__ int   g_off[NN + 1];
__device__ int   g_cur[NN];
__device__ int   g_blk[NBLK];
__device__ int   g_edge[NE];             // packed (src<<3)|efeat
// bf16-split operands, row-major [row][k] bf16 (pad rows stay zero)
__device__ unsigned char g_ah[IMG_BYTES];
__device__ unsigned char g_al[IMG_BYTES];
__device__ unsigned char g_wh[NL * DIM * ROW_BYTES];  // W^T: [n][k]
__device__ unsigned char g_wl[NL * DIM * ROW_BYTES];

// bf16 hi/lo split of a float pair, packed (low half = first element)
__device__ __forceinline__ void bsplit(float a, float b, uint32_t& hi, uint32_t& lo) {
    __nv_bfloat162 h = __float22bfloat162_rn(make_float2(a, b));
    float2 hf = __bfloat1622float2(h);
    __nv_bfloat162 l = __float22bfloat162_rn(make_float2(a - hf.x, b - hf.y));
    hi = *(uint32_t*)&h;
    lo = *(uint32_t*)&l;
}

__device__ __forceinline__ uint32_t smem_u32(const void* p) {
    uint32_t a;
    asm("{ .reg .u64 t; cvta.to.shared.u64 t, %1; cvt.u32.u64 %0, t; }"
        : "=r"(a) : "l"(p));
    return a;
}
__device__ __forceinline__ void ldsm4(uint32_t& r0, uint32_t& r1, uint32_t& r2,
                                      uint32_t& r3, uint32_t addr) {
    asm volatile("ldmatrix.sync.aligned.m8n8.x4.shared.b16 {%0,%1,%2,%3}, [%4];"
                 : "=r"(r0), "=r"(r1), "=r"(r2), "=r"(r3) : "r"(addr));
}
__device__ __forceinline__ void mma16816(float* d, uint32_t a0, uint32_t a1,
                                         uint32_t a2, uint32_t a3,
                                         uint32_t b0, uint32_t b1) {
    asm volatile(
        "mma.sync.aligned.m16n8k16.row.col.f32.bf16.bf16.f32 "
        "{%0,%1,%2,%3}, {%4,%5,%6,%7}, {%8,%9}, {%0,%1,%2,%3};"
        : "+f"(d[0]), "+f"(d[1]), "+f"(d[2]), "+f"(d[3])
        : "r"(a0), "r"(a1), "r"(a2), "r"(a3), "r"(b0), "r"(b1));
}
__device__ __forceinline__ void cpasync16(uint32_t saddr, const void* g) {
    asm volatile("cp.async.cg.shared.global [%0], [%1], 16;"
                 :: "r"(saddr), "l"(g) : "memory");
}

// ---------------- setup kernels ----------------
__global__ void k_init() {
    int idx = blockIdx.x * blockDim.x + threadIdx.x;
    if (idx < NL * 2 * DIM) g_statsL[idx] = 0.f;   // replay-safe stats re-zero
    if (idx < NN) g_cnti[idx] = 0;
}

__global__ void k_hist(const int* __restrict__ dst) {
    int e = blockIdx.x * blockDim.x + threadIdx.x;
    if (e < NE) atomicAdd(&g_cnti[dst[e]], 1);
}

__global__ void k_scan1() {
    __shared__ int s[256];
    int i = blockIdx.x * 256 + threadIdx.x;
    int c = (i < NN) ? g_cnti[i] : 0;
    s[threadIdx.x] = c;
    __syncthreads();
    int v = c;
#pragma unroll
    for (int d = 1; d < 256; d <<= 1) {
        int t = (threadIdx.x >= d) ? s[threadIdx.x - d] : 0;
        __syncthreads();
        v += t;
        s[threadIdx.x] = v;
        __syncthreads();
    }
    if (i < NN) g_off[i] = v - c;
    if (threadIdx.x == 255) g_blk[blockIdx.x] = v;
}

__global__ void k_scan2() {
    __shared__ int s[1024];
    int t = threadIdx.x;
    int c = (t < NBLK) ? g_blk[t] : 0;
    s[t] = c;
    __syncthreads();
    int v = c;
#pragma unroll
    for (int d = 1; d < 1024; d <<= 1) {
        int x = (t >= d) ? s[t - d] : 0;
        __syncthreads();
        v += x;
        s[t] = v;
        __syncthreads();
    }
    if (t < NBLK) g_blk[t] = v - c;
}

__global__ void k_scan3() {
    int i = blockIdx.x * blockDim.x + threadIdx.x;
    if (i >= NN) return;
    int off = g_off[i] + g_blk[i >> 8];
    g_off[i] = off;
    g_cur[i] = off;
    g_deg[i] = 1.0f / (float)(g_cnti[i] + 1);
    if (i == 0) g_off[NN] = NE;
}

__global__ void k_fill(const int* __restrict__ src, const int* __restrict__ dst,
                       const int* __restrict__ efeat) {
    int e = blockIdx.x * blockDim.x + threadIdx.x;
    if (e >= NE) return;
    int d = dst[e];
    int pos = atomicAdd(&g_cur[d], 1);
    g_edge[pos] = (src[e] << 3) | efeat[e];
}

// W^T images: BT[n][k] = W[k][n], bf16 hi/lo row-major
__global__ void k_wconv(const float* __restrict__ W) {
    int l = blockIdx.x, t = threadIdx.x;  // t = n
    const float* Wl = W + (size_t)l * DIM * DIM;
    unsigned char* wh = g_wh + (size_t)l * DIM * ROW_BYTES;
    unsigned char* wl = g_wl + (size_t)l * DIM * ROW_BYTES;
    for (int k = 0; k < DIM; k += 2) {
        uint32_t hi, lo;
        bsplit(Wl[k * DIM + t], Wl[(k + 1) * DIM + t], hi, lo);
        uint32_t byte = (uint32_t)(t * ROW_BYTES + k * 2);
        *(uint32_t*)(wh + byte) = hi;
        *(uint32_t*)(wl + byte) = lo;
    }
}

// ---------------- layer-0 aggregate: all features from smem tables ----------
// A0[n] = (emb[nf[n]] + sum_in (emb[nf[src]] + eemb[f])) * deg_inv[n]
#define AGG0_SMEM ((ATOMV * DIM + BONDV * DIM) * 4)   // 63488 bytes

__global__ void __launch_bounds__(256) k_agg0(const int* __restrict__ nfeat,
                                              const float* __restrict__ atom_emb,
                                              const float* __restrict__ eembL) {
    extern __shared__ float sm[];
    float4* emb4 = (float4*)sm;                       // ATOMV*32 float4
    float4* se4  = (float4*)(sm + ATOMV * DIM);       // BONDV*32 float4
    int tid = threadIdx.x;
    const int TOT4 = (ATOMV + BONDV) * 32;            // 3968
    for (int i = tid; i < TOT4; i += 256) {
        if (i < ATOMV * 32) emb4[i] = ((const float4*)atom_emb)[i];
        else                se4[i - ATOMV * 32] = ((const float4*)eembL)[i - ATOMV * 32];
    }
    __syncthreads();

    int wid = tid >> 5, c = tid & 31;
    int base = blockIdx.x * 128 + wid * 16;

#pragma unroll 1
    for (int i = 0; i < 16; i++) {
        int n = base + i;
        if (n >= NN) break;
        float4 acc = emb4[nfeat[n] * 32 + c];
        int p0 = g_off[n], p1 = g_off[n + 1];
        for (int p = p0; p < p1; p++) {
            int pk = g_edge[p];
            int s = pk >> 3, f = pk & 7;
            float4 v = emb4[nfeat[s] * 32 + c];
            float4 ev = se4[f * 32 + c];
            acc.x += v.x + ev.x;
            acc.y += v.y + ev.y;
            acc.z += v.z + ev.z;
            acc.w += v.w + ev.w;
        }
        float dinv = g_deg[n];
        acc.x *= dinv; acc.y *= dinv; acc.z *= dinv; acc.w *= dinv;
        uint2 hi2, lo2;
        bsplit(acc.x, acc.y, hi2.x, lo2.x);
        bsplit(acc.z, acc.w, hi2.y, lo2.y);
        size_t gb = (size_t)n * ROW_BYTES + c * 8;
        *(uint2*)(g_ah + gb) = hi2;
        *(uint2*)(g_al + gb) = lo2;
    }
}

// ---------------- layers 1..4 aggregate (reads g_y, inline BN) --------------
__global__ void __launch_bounds__(256) k_aggregate(const float* __restrict__ eembL,
                                                   const float* __restrict__ stats,
                                                   const float* __restrict__ gammaL,
                                                   const float* __restrict__ betaL) {
    __shared__ float se[BONDV * DIM];
    __shared__ float sbnp[2 * DIM];
    int tid = threadIdx.x;
    if (tid < BONDV * 32)
        ((float4*)se)[tid] = ((const float4*)eembL)[tid];
    if (tid < DIM) {
        float mu  = stats[tid] * (1.0f / NN);
        float var = stats[DIM + tid] * (1.0f / NN) - mu * mu;
        float rstd = rsqrtf(var + 1e-5f);
        float sc = rstd * gammaL[tid];
        sbnp[tid] = sc;
        sbnp[DIM + tid] = betaL[tid] - mu * sc;
    }
    __syncthreads();

    int n = blockIdx.x * 8 + (tid >> 5);
    if (n >= NN) return;
    int c = tid & 31;

    float4 sc = ((const float4*)sbnp)[c];
    float4 sh = ((const float4*)(sbnp + DIM))[c];

    const float4* y4 = (const float4*)g_y;
    const float4* se4 = (const float4*)se;

    float4 acc;
    {
        float4 v = y4[n * 32 + c];
        acc.x = fmaxf(fmaf(v.x, sc.x, sh.x), 0.f);
        acc.y = fmaxf(fmaf(v.y, sc.y, sh.y), 0.f);
        acc.z = fmaxf(fmaf(v.z, sc.z, sh.z), 0.f);
        acc.w = fmaxf(fmaf(v.w, sc.w, sh.w), 0.f);
    }

    int p0 = g_off[n], p1 = g_off[n + 1];
    for (int p = p0; p < p1; p++) {
        int pk = g_edge[p];
        int s = pk >> 3, f = pk & 7;
        float4 v = y4[s * 32 + c];
        float4 ev = se4[f * 32 + c];
        acc.x += fmaxf(fmaf(v.x, sc.x, sh.x), 0.f) + ev.x;
        acc.y += fmaxf(fmaf(v.y, sc.y, sh.y), 0.f) + ev.y;
        acc.z += fmaxf(fmaf(v.z, sc.z, sh.z), 0.f) + ev.z;
        acc.w += fmaxf(fmaf(v.w, sc.w, sh.w), 0.f) + ev.w;
    }
    float dinv = g_deg[n];
    acc.x *= dinv; acc.y *= dinv; acc.z *= dinv; acc.w *= dinv;

    uint2 hi2, lo2;
    bsplit(acc.x, acc.y, hi2.x, lo2.x);
    bsplit(acc.z, acc.w, hi2.y, lo2.y);
    size_t base = (size_t)n * ROW_BYTES + c * 8;
    *(uint2*)(g_ah + base) = hi2;
    *(uint2*)(g_al + base) = lo2;
}

// ---- tensor-core GEMM via mma.sync bf16 3-term split: y = A@W + b + stats --
#define PITCH2 144                // 64 bf16 (128B) rows padded to 9x16B
#define HIMG (128 * PITCH2)       // 18432 bytes per half-image
#define SM_BIAS 0
#define SM_SUM  512
#define SM_SQ   1024
#define SM_AH   1536
#define SM_AL   (SM_AH + HIMG)
#define SM_WH   (SM_AL + HIMG)
#define SM_WL   (SM_WH + HIMG)
#define SM_TOTAL (SM_WL + HIMG)   // 75264

__global__ void __launch_bounds__(256, 2) k_gemm(int layer, const float* __restrict__ bl) {
    extern __shared__ char smem[];
    uint32_t sb = smem_u32(smem);
    int tid = threadIdx.x, wid = tid >> 5, lane = tid & 31;
    int g = lane >> 2, tg = lane & 3;

    float* sbias = (float*)(smem + SM_BIAS);
    float* ssum  = (float*)(smem + SM_SUM);
    float* ssq   = (float*)(smem + SM_SQ);
    if (tid < 128) {
        sbias[tid] = bl[tid];
        ssum[tid] = 0.f;
        ssq[tid] = 0.f;
    }

    const float4* gah = (const float4*)(g_ah + (size_t)blockIdx.x * 128 * ROW_BYTES);
    const float4* gal = (const float4*)(g_al + (size_t)blockIdx.x * 128 * ROW_BYTES);
    const float4* gwh = (const float4*)(g_wh + (size_t)layer * DIM * ROW_BYTES);
    const float4* gwl = (const float4*)(g_wl + (size_t)layer * DIM * ROW_BYTES);

    uint32_t a_row = 16 * wid + (lane & 15);
    uint32_t a_kof = (lane >> 4) * 16;
    uint32_t ah_base = sb + SM_AH + a_row * PITCH2 + a_kof;
    uint32_t al_base = sb + SM_AL + a_row * PITCH2 + a_kof;
    uint32_t b_row = ((lane >> 4) << 3) + (lane & 7);
    uint32_t b_kof = ((lane >> 3) & 1) * 16;
    uint32_t wh_base = sb + SM_WH + b_row * PITCH2 + b_kof;
    uint32_t wl_base = sb + SM_WL + b_row * PITCH2 + b_kof;

    float d[16][4];
#pragma unroll
    for (int i = 0; i < 16; i++)
#pragma unroll
        for (int j = 0; j < 4; j++) d[i][j] = 0.f;

#pragma unroll
    for (int kh = 0; kh < 2; kh++) {
#pragma unroll
        for (int i = 0; i < 4; i++) {
            int idx = tid + i * 256;
            int row = idx >> 3, q = idx & 7;
            int gidx = row * 16 + kh * 8 + q;
            uint32_t soff = row * PITCH2 + q * 16;
            cpasync16(sb + SM_AH + soff, gah + gidx);
            cpasync16(sb + SM_AL + soff, gal + gidx);
            cpasync16(sb + SM_WH + soff, gwh + gidx);
            cpasync16(sb + SM_WL + soff, gwl + gidx);
        }
        asm volatile("cp.async.commit_group;" ::: "memory");
        asm volatile("cp.async.wait_group 0;" ::: "memory");
        __syncthreads();

#pragma unroll
        for (int ks = 0; ks < 4; ks++) {
            uint32_t ah0, ah1, ah2, ah3, al0, al1, al2, al3;
            ldsm4(ah0, ah1, ah2, ah3, ah_base + ks * 32);
            ldsm4(al0, al1, al2, al3, al_base + ks * 32);
#pragma unroll
            for (int nt2 = 0; nt2 < 8; nt2++) {
                uint32_t bh0, bh1, bh2, bh3, bl0_, bl1_, bl2_, bl3_;
                uint32_t off = nt2 * 16 * PITCH2 + ks * 32;
                ldsm4(bh0, bh1, bh2, bh3, wh_base + off);
                ldsm4(bl0_, bl1_, bl2_, bl3_, wl_base + off);
                mma16816(d[2 * nt2], ah0, ah1, ah2, ah3, bh0, bh1);
                mma16816(d[2 * nt2], al0, al1, al2, al3, bh0, bh1);
                mma16816(d[2 * nt2], ah0, ah1, ah2, ah3, bl0_, bl1_);
                mma16816(d[2 * nt2 + 1], ah0, ah1, ah2, ah3, bh2, bh3);
                mma16816(d[2 * nt2 + 1], al0, al1, al2, al3, bh2, bh3);
                mma16816(d[2 * nt2 + 1], ah0, ah1, ah2, ah3, bl2_, bl3_);
            }
        }
        __syncthreads();
    }

    int row0 = blockIdx.x * 128 + 16 * wid + g;
    int row1 = row0 + 8;
    bool v0 = row0 < NN, v1 = row1 < NN;

#pragma unroll
    for (int nt = 0; nt < 16; nt++) {
        int c0 = nt * 8 + 2 * tg;
        float b0 = sbias[c0], b1 = sbias[c0 + 1];
        float y0 = d[nt][0] + b0, y1 = d[nt][1] + b1;
        float y2 = d[nt][2] + b0, y3 = d[nt][3] + b1;
        if (!v0) { y0 = 0.f; y1 = 0.f; }
        if (!v1) { y2 = 0.f; y3 = 0.f; }
        if (v0) *(float2*)&g_y[(size_t)row0 * DIM + c0] = make_float2(y0, y1);
        if (v1) *(float2*)&g_y[(size_t)row1 * DIM + c0] = make_float2(y2, y3);

        float s0 = y0 + y2, s1 = y1 + y3;
        float q0 = y0 * y0 + y2 * y2, q1 = y1 * y1 + y3 * y3;
#pragma unroll
        for (int m = 4; m <= 16; m <<= 1) {
            s0 += __shfl_xor_sync(0xffffffffu, s0, m);
            s1 += __shfl_xor_sync(0xffffffffu, s1, m);
            q0 += __shfl_xor_sync(0xffffffffu, q0, m);
            q1 += __shfl_xor_sync(0xffffffffu, q1, m);
        }
        if (lane < 4) {
            atomicAdd(&ssum[c0], s0);
            atomicAdd(&ssum[c0 + 1], s1);
            atomicAdd(&ssq[c0], q0);
            atomicAdd(&ssq[c0 + 1], q1);
        }
    }
    __syncthreads();
    if (tid < 128) {
        float* st = g_statsL + layer * 2 * DIM;
        atomicAdd(&st[tid], ssum[tid]);
        atomicAdd(&st[DIM + tid], ssq[tid]);
    }
}

// ---------------- fused pool + MLP (n2g sorted); applies final BN+relu ------
__device__ __forceinline__ int lbound(const int* __restrict__ a, int n, int key) {
    int lo = 0, hi = n;
    while (lo < hi) {
        int mid = (lo + hi) >> 1;
        if (a[mid] < key) lo = mid + 1; else hi = mid;
    }
    return lo;
}

__global__ void __launch_bounds__(128) k_poolmlp(const int* __restrict__ n2g,
                                                 const float* __restrict__ stats,
                                                 const float* __restrict__ gammaL,
                                                 const float* __restrict__ betaL,
                                                 const float* __restrict__ W1,
                                                 const float* __restrict__ b1,
                                                 const float* __restrict__ W2,
                                                 const float* __restrict__ b2,
                                                 float* __restrict__ out) {
    __shared__ int range[2];
    __shared__ float gs[DIM], ts[DIM];
    int gid = blockIdx.x, t = threadIdx.x;
    if (t < 2) range[t] = lbound(n2g, NN, gid + t);
    __syncthreads();
    int s = range[0], e = range[1];

    float mu  = stats[t] * (1.0f / NN);
    float var = stats[DIM + t] * (1.0f / NN) - mu * mu;
    float rstd = rsqrtf(var + 1e-5f);
    float sc = rstd * gammaL[t];
    float sh = betaL[t] - mu * sc;

    float sum = 0.f;
    for (int n = s; n < e; n++)
        sum += fmaxf(fmaf(g_y[(size_t)n * DIM + t], sc, sh), 0.f);
    float cnt = fmaxf((float)(e - s), 1.0f);
    gs[t] = sum / cnt;
    __syncthreads();

    float acc = b1[t];
#pragma unroll 4
    for (int k = 0; k < DIM; k++) acc = fmaf(gs[k], W1[k * DIM + t], acc);
    ts[t] = fmaxf(acc, 0.f);
    __syncthreads();
    float acc2 = b2[t];
#pragma unroll 4
    for (int k = 0; k < DIM; k++) acc2 = fmaf(ts[k], W2[k * DIM + t], acc2);
    out[gid * DIM + t] = acc2;
}

// ---------------- launcher ----------------
extern "C" void kernel_launch(void* const* d_in, const int* in_sizes, int n_in,
                              void* d_out, int out_size) {
    const int*   nfeat    = (const int*)d_in[0];
    const int*   efeat    = (const int*)d_in[1];
    const int*   src      = (const int*)d_in[2];
    const int*   dst      = (const int*)d_in[3];
    const int*   n2g      = (const int*)d_in[4];
    const float* atom_emb = (const float*)d_in[5];
    const float* edge_emb = (const float*)d_in[6];
    const float* W        = (const float*)d_in[7];
    const float* b        = (const float*)d_in[8];
    const float* gamma    = (const float*)d_in[9];
    const float* beta     = (const float*)d_in[10];
    const float* W1       = (const float*)d_in[11];
    const float* b1       = (const float*)d_in[12];
    const float* W2       = (const float*)d_in[13];
    const float* b2       = (const float*)d_in[14];
    float* out = (float*)d_out;

    static bool attr_set = false;
    if (!attr_set) {
        cudaFuncSetAttribute(k_gemm, cudaFuncAttributeMaxDynamicSharedMemorySize,
                             SM_TOTAL);
        cudaFuncSetAttribute(k_agg0, cudaFuncAttributeMaxDynamicSharedMemorySize,
                             AGG0_SMEM);
        attr_set = true;
    }

    float* statsL = nullptr;
    cudaGetSymbolAddress((void**)&statsL, g_statsL);

    const int nthr = 256;
    int gEdge = (NE + nthr - 1) / nthr;
    int gNode = (NN + nthr - 1) / nthr;

    k_init<<<gNode, nthr>>>();
    k_hist<<<gEdge, nthr>>>(dst);
    k_wconv<<<NL, 128>>>(W);
    k_scan1<<<NBLK, 256>>>();
    k_scan2<<<1, 1024>>>();
    k_scan3<<<gNode, nthr>>>();
    k_fill<<<gEdge, nthr>>>(src, dst, efeat);

    for (int l = 0; l < NL; l++) {
        if (l == 0)
            k_agg0<<<NTILE, 256, AGG0_SMEM>>>(nfeat, atom_emb, edge_emb);
        else
            k_aggregate<<<(NN + 7) / 8, 256>>>(
                edge_emb + (size_t)l * BONDV * DIM,
                statsL + (size_t)(l - 1) * 2 * DIM,
                gamma + (size_t)(l - 1) * DIM,
                beta + (size_t)(l - 1) * DIM);
        k_gemm<<<NTILE, 256, SM_TOTAL>>>(l, b + (size_t)l * DIM);
    }

    k_poolmlp<<<NG, 128>>>(n2g,
                           statsL + (size_t)(NL - 1) * 2 * DIM,
                           gamma + (size_t)(NL - 1) * DIM,
                           beta + (size_t)(NL - 1) * DIM,
                           W1, b1, W2, b2, out);
}